// round 13
// baseline (speedup 1.0000x reference)
#include <cuda_runtime.h>
#include <cuda_bf16.h>

// cos_t [4096, 100000] fp32, y_true [4096,1] int64-or-int32.
// Output: [cos_t passthrough (N*C floats)][mean scalar].
//
// FINAL (converged): pure HBM-roofline stream (1.64 GB read + 1.64 GB write,
// both mandatory — d_out is poisoned by the harness). SM-side float4
// streaming copy sustains ~6.8 TB/s (86% DRAM util, the measured GB300
// mixed-stream ceiling; invariant across occupancy 43-95%, MLP 1-8,
// grid 296-4096, block 512/1024, tail shape). Gather+mean fused into
// block 0 at zero cost. CE memcpy path is 2.1x slower — do not revert.

#define N_ROWS 4096
#define C_COLS 100000

__global__ __launch_bounds__(1024)
void fused_copy_gather_kernel(const float4* __restrict__ src4,
                              float4* __restrict__ dst4,
                              const float* __restrict__ cos_t,
                              const int* __restrict__ y_words,
                              float* __restrict__ out_scalar,
                              long long n4) {
    int tid = threadIdx.x;

    // ---- Block 0: gather + mean (then joins the copy) ----
    if (blockIdx.x == 0) {
        __shared__ float sdata[1024];
        __shared__ int is_int64;
        if (tid < 32) {
            // int64 labels < 2^31 have zero hi-words at odd int32 indices.
            int w = y_words[2 * tid + 1];
            unsigned ballot = __ballot_sync(0xFFFFFFFFu, w != 0);
            if (tid == 0) is_int64 = (ballot == 0u) ? 1 : 0;
        }
        __syncthreads();
        const bool i64 = (is_int64 != 0);

        float acc = 0.0f;
        #pragma unroll
        for (int k = 0; k < 4; k++) {
            int row = tid + k * 1024;
            long long col = i64 ? (long long)y_words[2 * row]
                                : (long long)y_words[row];
            if (col < 0) col = 0;
            if (col >= C_COLS) col = C_COLS - 1;
            acc += cos_t[(long long)row * C_COLS + col];
        }
        sdata[tid] = acc;
        __syncthreads();
        for (int s = 512; s > 0; s >>= 1) {
            if (tid < s) sdata[tid] += sdata[tid + s];
            __syncthreads();
        }
        if (tid == 0) *out_scalar = sdata[0] / (float)N_ROWS;
    }

    // ---- All blocks: grid-stride streaming copy, 4x batched MLP ----
    const long long base   = (long long)blockIdx.x * blockDim.x + tid;
    const long long stride = (long long)gridDim.x * blockDim.x;

    long long i = base;
    for (; i + 3 * stride < n4; i += 4 * stride) {
        float4 a = __ldcs(&src4[i]);
        float4 b = __ldcs(&src4[i + stride]);
        float4 c = __ldcs(&src4[i + 2 * stride]);
        float4 d = __ldcs(&src4[i + 3 * stride]);
        __stcs(&dst4[i],              a);
        __stcs(&dst4[i + stride],     b);
        __stcs(&dst4[i + 2 * stride], c);
        __stcs(&dst4[i + 3 * stride], d);
    }
    for (; i < n4; i += stride) {
        __stcs(&dst4[i], __ldcs(&src4[i]));
    }
}

extern "C" void kernel_launch(void* const* d_in, const int* in_sizes, int n_in,
                              void* d_out, int out_size) {
    // Identify inputs by element count.
    long long big = -1;
    int big_i = 0, small_i = 1;
    for (int i = 0; i < n_in; i++)
        if ((long long)in_sizes[i] > big) { big = in_sizes[i]; big_i = i; }
    for (int i = 0; i < n_in; i++) if (i != big_i) { small_i = i; break; }

    const float* cos_t = (const float*)d_in[big_i];
    const int*   y_w   = (const int*)d_in[small_i];
    float* out = (float*)d_out;

    const long long total = (long long)N_ROWS * (long long)C_COLS; // 409,600,000
    const long long n4 = total / 4;

    fused_copy_gather_kernel<<<2048, 1024>>>(
        (const float4*)cos_t, (float4*)out,
        cos_t, y_w, out + total, n4);
}

// round 14
// speedup vs baseline: 1.0009x; 1.0009x over previous
#include <cuda_runtime.h>
#include <cuda_bf16.h>

// cos_t [4096, 100000] fp32, y_true [4096,1] int64-or-int32.
// Output: [cos_t passthrough (N*C floats)][mean scalar].
//
// FINAL (converged): pure HBM-roofline stream (1.64 GB read + 1.64 GB write,
// both mandatory — d_out is poisoned by the harness). SM-side float4
// streaming copy sustains ~6.8 TB/s (86% DRAM util, the measured GB300
// mixed-stream ceiling; invariant across occupancy 43-95%, MLP 1-8,
// grid 296-4096, block 512/1024, tail shape, 10 consecutive runs).
// Gather+mean fused into block 0 at zero cost. CE memcpy path is 2.1x
// slower — do not revert.

#define N_ROWS 4096
#define C_COLS 100000

__global__ __launch_bounds__(1024)
void fused_copy_gather_kernel(const float4* __restrict__ src4,
                              float4* __restrict__ dst4,
                              const float* __restrict__ cos_t,
                              const int* __restrict__ y_words,
                              float* __restrict__ out_scalar,
                              long long n4) {
    int tid = threadIdx.x;

    // ---- Block 0: gather + mean (then joins the copy) ----
    if (blockIdx.x == 0) {
        __shared__ float sdata[1024];
        __shared__ int is_int64;
        if (tid < 32) {
            // int64 labels < 2^31 have zero hi-words at odd int32 indices.
            int w = y_words[2 * tid + 1];
            unsigned ballot = __ballot_sync(0xFFFFFFFFu, w != 0);
            if (tid == 0) is_int64 = (ballot == 0u) ? 1 : 0;
        }
        __syncthreads();
        const bool i64 = (is_int64 != 0);

        float acc = 0.0f;
        #pragma unroll
        for (int k = 0; k < 4; k++) {
            int row = tid + k * 1024;
            long long col = i64 ? (long long)y_words[2 * row]
                                : (long long)y_words[row];
            if (col < 0) col = 0;
            if (col >= C_COLS) col = C_COLS - 1;
            acc += cos_t[(long long)row * C_COLS + col];
        }
        sdata[tid] = acc;
        __syncthreads();
        for (int s = 512; s > 0; s >>= 1) {
            if (tid < s) sdata[tid] += sdata[tid + s];
            __syncthreads();
        }
        if (tid == 0) *out_scalar = sdata[0] / (float)N_ROWS;
    }

    // ---- All blocks: grid-stride streaming copy, 4x batched MLP ----
    const long long base   = (long long)blockIdx.x * blockDim.x + tid;
    const long long stride = (long long)gridDim.x * blockDim.x;

    long long i = base;
    for (; i + 3 * stride < n4; i += 4 * stride) {
        float4 a = __ldcs(&src4[i]);
        float4 b = __ldcs(&src4[i + stride]);
        float4 c = __ldcs(&src4[i + 2 * stride]);
        float4 d = __ldcs(&src4[i + 3 * stride]);
        __stcs(&dst4[i],              a);
        __stcs(&dst4[i + stride],     b);
        __stcs(&dst4[i + 2 * stride], c);
        __stcs(&dst4[i + 3 * stride], d);
    }
    for (; i < n4; i += stride) {
        __stcs(&dst4[i], __ldcs(&src4[i]));
    }
}

extern "C" void kernel_launch(void* const* d_in, const int* in_sizes, int n_in,
                              void* d_out, int out_size) {
    // Identify inputs by element count.
    long long big = -1;
    int big_i = 0, small_i = 1;
    for (int i = 0; i < n_in; i++)
        if ((long long)in_sizes[i] > big) { big = in_sizes[i]; big_i = i; }
    for (int i = 0; i < n_in; i++) if (i != big_i) { small_i = i; break; }

    const float* cos_t = (const float*)d_in[big_i];
    const int*   y_w   = (const int*)d_in[small_i];
    float* out = (float*)d_out;

    const long long total = (long long)N_ROWS * (long long)C_COLS; // 409,600,000
    const long long n4 = total / 4;

    fused_copy_gather_kernel<<<2048, 1024>>>(
        (const float4*)cos_t, (float4*)out,
        cos_t, y_w, out + total, n4);
}

// round 15
// speedup vs baseline: 1.0022x; 1.0013x over previous
#include <cuda_runtime.h>
#include <cuda_bf16.h>

// cos_t [4096, 100000] fp32, y_true [4096,1] int64-or-int32.
// Output: [cos_t passthrough (N*C floats)][mean scalar].
//
// FINAL (converged): pure HBM-roofline stream (1.64 GB read + 1.64 GB write,
// both mandatory — d_out is poisoned by the harness). SM-side float4
// streaming copy sustains ~6.8 TB/s (86% DRAM util, the measured GB300
// mixed-stream ceiling; invariant across occupancy 43-95%, MLP 1-8,
// grid 296-4096, block 512/1024, tail shape, 11 consecutive runs).
// Gather+mean fused into block 0 at zero cost. CE memcpy path is 2.1x
// slower — do not revert.

#define N_ROWS 4096
#define C_COLS 100000

__global__ __launch_bounds__(1024)
void fused_copy_gather_kernel(const float4* __restrict__ src4,
                              float4* __restrict__ dst4,
                              const float* __restrict__ cos_t,
                              const int* __restrict__ y_words,
                              float* __restrict__ out_scalar,
                              long long n4) {
    int tid = threadIdx.x;

    // ---- Block 0: gather + mean (then joins the copy) ----
    if (blockIdx.x == 0) {
        __shared__ float sdata[1024];
        __shared__ int is_int64;
        if (tid < 32) {
            // int64 labels < 2^31 have zero hi-words at odd int32 indices.
            int w = y_words[2 * tid + 1];
            unsigned ballot = __ballot_sync(0xFFFFFFFFu, w != 0);
            if (tid == 0) is_int64 = (ballot == 0u) ? 1 : 0;
        }
        __syncthreads();
        const bool i64 = (is_int64 != 0);

        float acc = 0.0f;
        #pragma unroll
        for (int k = 0; k < 4; k++) {
            int row = tid + k * 1024;
            long long col = i64 ? (long long)y_words[2 * row]
                                : (long long)y_words[row];
            if (col < 0) col = 0;
            if (col >= C_COLS) col = C_COLS - 1;
            acc += cos_t[(long long)row * C_COLS + col];
        }
        sdata[tid] = acc;
        __syncthreads();
        for (int s = 512; s > 0; s >>= 1) {
            if (tid < s) sdata[tid] += sdata[tid + s];
            __syncthreads();
        }
        if (tid == 0) *out_scalar = sdata[0] / (float)N_ROWS;
    }

    // ---- All blocks: grid-stride streaming copy, 4x batched MLP ----
    const long long base   = (long long)blockIdx.x * blockDim.x + tid;
    const long long stride = (long long)gridDim.x * blockDim.x;

    long long i = base;
    for (; i + 3 * stride < n4; i += 4 * stride) {
        float4 a = __ldcs(&src4[i]);
        float4 b = __ldcs(&src4[i + stride]);
        float4 c = __ldcs(&src4[i + 2 * stride]);
        float4 d = __ldcs(&src4[i + 3 * stride]);
        __stcs(&dst4[i],              a);
        __stcs(&dst4[i + stride],     b);
        __stcs(&dst4[i + 2 * stride], c);
        __stcs(&dst4[i + 3 * stride], d);
    }
    for (; i < n4; i += stride) {
        __stcs(&dst4[i], __ldcs(&src4[i]));
    }
}

extern "C" void kernel_launch(void* const* d_in, const int* in_sizes, int n_in,
                              void* d_out, int out_size) {
    // Identify inputs by element count.
    long long big = -1;
    int big_i = 0, small_i = 1;
    for (int i = 0; i < n_in; i++)
        if ((long long)in_sizes[i] > big) { big = in_sizes[i]; big_i = i; }
    for (int i = 0; i < n_in; i++) if (i != big_i) { small_i = i; break; }

    const float* cos_t = (const float*)d_in[big_i];
    const int*   y_w   = (const int*)d_in[small_i];
    float* out = (float*)d_out;

    const long long total = (long long)N_ROWS * (long long)C_COLS; // 409,600,000
    const long long n4 = total / 4;

    fused_copy_gather_kernel<<<2048, 1024>>>(
        (const float4*)cos_t, (float4*)out,
        cos_t, y_w, out + total, n4);
}